// round 2
// baseline (speedup 1.0000x reference)
#include <cuda_runtime.h>
#include <math.h>

#define BB 256
#define TT 128
#define HH 256
#define FF 16
#define GG 1040   // 4*H + F

// ---- static device scratch ----
__device__ float g_xproj[TT * GG * BB];   // [t][g][b]
__device__ float g_h[2][HH * BB];         // [j][b], double buffered
__device__ float g_Sre[BB * HH * FF];     // [(b*H+j)*F + f]
__device__ float g_Sim[BB * HH * FF];

__device__ __forceinline__ float hsig(float x) {
    return __saturatef(x * 0.16666667f + 0.5f);
}

// ---------------- init ----------------
__global__ void init_kernel() {
    int i = blockIdx.x * blockDim.x + threadIdx.x;
    int n = blockDim.x * gridDim.x;
    for (int k = i; k < 2 * HH * BB; k += n) (&g_h[0][0])[k] = 0.f;
    for (int k = i; k < BB * HH * FF; k += n) { g_Sre[k] = 0.f; g_Sim[k] = 0.f; }
}

// ---------------- phase 0: input projection ----------------
// xproj[t][g][b] = sum_k X[b,t,k] * W[k,g] + bias[g]
// grid (17 g-tiles of 64, 4 b-tiles of 64, 128 t), 128 threads
__global__ void proj_kernel(
    const float* __restrict__ sig, const float* __restrict__ met,
    const float* __restrict__ Wis, const float* __restrict__ Wss, const float* __restrict__ Wfs,
    const float* __restrict__ Wcs, const float* __restrict__ Wos,
    const float* __restrict__ Wim, const float* __restrict__ Wsm, const float* __restrict__ Wfm,
    const float* __restrict__ Wcm, const float* __restrict__ Wom,
    const float* __restrict__ b_i, const float* __restrict__ b_ste, const float* __restrict__ b_fre,
    const float* __restrict__ b_c, const float* __restrict__ b_o)
{
    __shared__ float A_s[96 * 64];   // [k][b]
    __shared__ float B_s[96 * 64];   // [k][n]
    const int n0 = blockIdx.x * 64;
    const int b0 = blockIdx.y * 64;
    const int t  = blockIdx.z;
    const int tid = threadIdx.x;

    // stage A: rows of 96 (64 sig + 32 met) per b
    for (int idx = tid; idx < 64 * 96; idx += 128) {
        int b = idx / 96, k = idx - b * 96;
        float v = (k < 64) ? sig[((b0 + b) * TT + t) * 64 + k]
                           : met[((b0 + b) * TT + t) * 32 + (k - 64)];
        A_s[k * 64 + b] = v;
    }
    // stage B: weight columns for this g-tile
    for (int idx = tid; idx < 96 * 64; idx += 128) {
        int k = idx >> 6, n = idx & 63;
        int g = n0 + n;
        float v = 0.f;
        if (g < 1024) {
            int gate = g >> 8, j = g & 255;
            const float* Ws = (gate == 0) ? Wis : (gate == 1) ? Wss : (gate == 2) ? Wcs : Wos;
            const float* Wm = (gate == 0) ? Wim : (gate == 1) ? Wsm : (gate == 2) ? Wcm : Wom;
            v = (k < 64) ? Ws[k * 256 + j] : Wm[(k - 64) * 256 + j];
        } else if (g < 1040) {
            int f = g - 1024;
            v = (k < 64) ? Wfs[k * 16 + f] : Wfm[(k - 64) * 16 + f];
        }
        B_s[k * 64 + n] = v;
    }
    __syncthreads();

    const int tm = tid & 7, tn = tid >> 3;   // 8 b-octets x 16 g-quads
    const int mb = tm * 8, nb = tn * 4;
    float acc[8][4] = {};
    for (int k = 0; k < 96; k++) {
        float4 a0 = *(const float4*)&A_s[k * 64 + mb];
        float4 a1 = *(const float4*)&A_s[k * 64 + mb + 4];
        float4 bv = *(const float4*)&B_s[k * 64 + nb];
        float am[8] = {a0.x, a0.y, a0.z, a0.w, a1.x, a1.y, a1.z, a1.w};
#pragma unroll
        for (int i = 0; i < 8; i++) {
            acc[i][0] += am[i] * bv.x; acc[i][1] += am[i] * bv.y;
            acc[i][2] += am[i] * bv.z; acc[i][3] += am[i] * bv.w;
        }
    }
#pragma unroll
    for (int q = 0; q < 4; q++) {
        int g = n0 + nb + q;
        if (g >= GG) continue;
        float bias;
        if (g < 1024) {
            int gate = g >> 8, j = g & 255;
            bias = (gate == 0) ? b_i[j] : (gate == 1) ? b_ste[j] : (gate == 2) ? b_c[j] : b_o[j];
        } else {
            bias = b_fre[g - 1024];
        }
        float4 w0, w1;
        w0.x = acc[0][q] + bias; w0.y = acc[1][q] + bias;
        w0.z = acc[2][q] + bias; w0.w = acc[3][q] + bias;
        w1.x = acc[4][q] + bias; w1.y = acc[5][q] + bias;
        w1.z = acc[6][q] + bias; w1.w = acc[7][q] + bias;
        float* dst = &g_xproj[(t * GG + g) * BB + b0 + mb];
        *(float4*)dst = w0;
        *(float4*)(dst + 4) = w1;
    }
}

// ---------------- per-step fused recurrence ----------------
// grid (8 b-tiles of 32, 16 j-tiles of 16), 128 threads, dynamic smem
#define STEP_SMEM_FLOATS (256*36 + 256*64 + 256*16 + 64*33 + 32*17 + 48)

__global__ void step_kernel(int t,
    const float* __restrict__ U_i, const float* __restrict__ U_ste,
    const float* __restrict__ U_c, const float* __restrict__ U_o,
    const float* __restrict__ U_fre, const float* __restrict__ U_a,
    const float* __restrict__ b_a)
{
    extern __shared__ float smn[];
    float* h_s   = smn;                 // [k=256][36] (32 b + pad)
    float* U_s   = h_s + 256 * 36;      // [k=256][64]  g = gate*16+jj
    float* Uf_s  = U_s + 256 * 64;      // [k=256][16]
    float* gt_s  = Uf_s + 256 * 16;     // [64][33]  gate pre-acts [g][b]
    float* fre_s = gt_s + 64 * 33;      // [32][17]
    float* re_s  = fre_s + 32 * 17;     // [16]
    float* im_s  = re_s + 16;
    float* Ua_s  = im_s + 16;

    const int b0 = blockIdx.x * 32;
    const int j0 = blockIdx.y * 16;
    const int tid = threadIdx.x;
    const float* hin = &g_h[t & 1][0];          // [j][b]
    float* hout = &g_h[(t & 1) ^ 1][0];

    // stage h: h_s[k][b] = hin[k*256 + b0+b]  (coalesced, conflict-free STS)
    for (int idx = tid; idx < 256 * 32; idx += 128) {
        int b = idx & 31, k = idx >> 5;
        h_s[k * 36 + b] = hin[k * 256 + b0 + b];
    }
    // stage U columns for this j-tile (4 gates x 16 cols)
    for (int idx = tid; idx < 256 * 16; idx += 128) {
        int k = idx >> 4, g4 = idx & 15;
        int gate = g4 >> 2, jq = g4 & 3;
        const float* U = (gate == 0) ? U_i : (gate == 1) ? U_ste : (gate == 2) ? U_c : U_o;
        float4 v = *(const float4*)&U[k * 256 + j0 + jq * 4];
        *(float4*)&U_s[k * 64 + gate * 16 + jq * 4] = v;
    }
    // stage U_fre (contiguous 4096 floats)
    for (int idx = tid; idx < 1024; idx += 128) {
        *(float4*)&Uf_s[idx * 4] = *(const float4*)&U_fre[idx * 4];
    }
    if (tid < 16) {
        float tw = 6.2831855f * (float)(t + 1);
        float ang = tw * ((float)tid * 0.0625f);
        float s, c;
        sincosf(ang, &s, &c);
        re_s[tid] = c; im_s[tid] = s;
        Ua_s[tid] = U_a[tid];
    }
    __syncthreads();

    // ---- GEMM: gt[b][g] = sum_k h[b][k] * U[k][g] ----
    {
        const int bg = tid >> 4, gg = tid & 15;
        const int bb = bg * 4, gb = gg * 4;
        float acc[4][4] = {};
#pragma unroll 4
        for (int k = 0; k < 256; k++) {
            float4 hv = *(const float4*)&h_s[k * 36 + bb];
            float4 uv = *(const float4*)&U_s[k * 64 + gb];
            acc[0][0] += hv.x * uv.x; acc[0][1] += hv.x * uv.y; acc[0][2] += hv.x * uv.z; acc[0][3] += hv.x * uv.w;
            acc[1][0] += hv.y * uv.x; acc[1][1] += hv.y * uv.y; acc[1][2] += hv.y * uv.z; acc[1][3] += hv.y * uv.w;
            acc[2][0] += hv.z * uv.x; acc[2][1] += hv.z * uv.y; acc[2][2] += hv.z * uv.z; acc[2][3] += hv.z * uv.w;
            acc[3][0] += hv.w * uv.x; acc[3][1] += hv.w * uv.y; acc[3][2] += hv.w * uv.z; acc[3][3] += hv.w * uv.w;
        }
#pragma unroll
        for (int q = 0; q < 4; q++)
#pragma unroll
            for (int i = 0; i < 4; i++)
                gt_s[(gb + q) * 33 + bb + i] = acc[i][q];
    }
    // ---- fre gate: fre[b][f] = hsig(x_fre + sum_k h[b][k]*Uf[k][f]) ----
    {
        const int fb = tid >> 2, f4 = tid & 3;
        float fa0 = 0.f, fa1 = 0.f, fa2 = 0.f, fa3 = 0.f;
#pragma unroll 4
        for (int k = 0; k < 256; k++) {
            float hk = h_s[k * 36 + fb];
            float4 uf = *(const float4*)&Uf_s[k * 16 + f4 * 4];
            fa0 += hk * uf.x; fa1 += hk * uf.y; fa2 += hk * uf.z; fa3 += hk * uf.w;
        }
        int xbase = (t * GG + 1024 + f4 * 4) * BB + b0 + fb;
        fre_s[fb * 17 + f4 * 4 + 0] = hsig(fa0 + g_xproj[xbase + 0 * BB]);
        fre_s[fb * 17 + f4 * 4 + 1] = hsig(fa1 + g_xproj[xbase + 1 * BB]);
        fre_s[fb * 17 + f4 * 4 + 2] = hsig(fa2 + g_xproj[xbase + 2 * BB]);
        fre_s[fb * 17 + f4 * 4 + 3] = hsig(fa3 + g_xproj[xbase + 3 * BB]);
    }
    __syncthreads();

    // ---- elementwise S update + h output ----
    {
        const int bq = tid & 7, jj = tid >> 3;
        const int j = j0 + jj;
        const float ba = b_a[j];
#pragma unroll
        for (int i = 0; i < 4; i++) {
            int b = bq + i * 8;
            int gb2 = b0 + b;
            int xrow = t * GG;
            float gi  = hsig(gt_s[jj * 33 + b]        + g_xproj[(xrow + j) * BB + gb2]);
            float ste = hsig(gt_s[(16 + jj) * 33 + b] + g_xproj[(xrow + 256 + j) * BB + gb2]);
            float cg  = gi * tanhf(gt_s[(32 + jj) * 33 + b] + g_xproj[(xrow + 512 + j) * BB + gb2]);
            float o   = hsig(gt_s[(48 + jj) * 33 + b] + g_xproj[(xrow + 768 + j) * BB + gb2]);
            int sb = (gb2 * 256 + j) * 16;
            float Aa = 0.f;
#pragma unroll
            for (int q = 0; q < 4; q++) {
                float4 sr = *(float4*)&g_Sre[sb + q * 4];
                float4 si = *(float4*)&g_Sim[sb + q * 4];
#pragma unroll
                for (int w = 0; w < 4; w++) {
                    int f = q * 4 + w;
                    float fv = ste * fre_s[b * 17 + f];
                    float* srp = &((float*)&sr)[w];
                    float* sip = &((float*)&si)[w];
                    float nr = fv * (*srp) + cg * re_s[f];
                    float ni = fv * (*sip) + cg * im_s[f];
                    *srp = nr; *sip = ni;
                    Aa += (nr * nr + ni * ni) * Ua_s[f];
                }
                *(float4*)&g_Sre[sb + q * 4] = sr;
                *(float4*)&g_Sim[sb + q * 4] = si;
            }
            float a = tanhf(Aa + ba);
            hout[j * 256 + gb2] = o * a;
        }
    }
}

// ---------------- output head ----------------
__global__ void final_kernel(const float* __restrict__ W_p, const float* __restrict__ b_p,
                             const float* __restrict__ fc_w, const float* __restrict__ fc_b,
                             float* __restrict__ out)
{
    int b = threadIdx.x;
    const float* h = &g_h[0][0];   // after 128 steps, final h is in buffer 0
    float s = 0.f;
    for (int j = 0; j < 256; j++) s += h[j * 256 + b] * W_p[j];
    float p = s + b_p[0];
    out[b] = p * fc_w[0] + fc_b[0];
}

// ---------------- launch ----------------
extern "C" void kernel_launch(void* const* d_in, const int* in_sizes, int n_in,
                              void* d_out, int out_size)
{
    const float* sig  = (const float*)d_in[0];
    const float* met  = (const float*)d_in[1];
    const float* Wis  = (const float*)d_in[2];
    const float* Wss  = (const float*)d_in[3];
    const float* Wfs  = (const float*)d_in[4];
    const float* Wcs  = (const float*)d_in[5];
    const float* Wos  = (const float*)d_in[6];
    const float* Wim  = (const float*)d_in[7];
    const float* Wsm  = (const float*)d_in[8];
    const float* Wfm  = (const float*)d_in[9];
    const float* Wcm  = (const float*)d_in[10];
    const float* Wom  = (const float*)d_in[11];
    const float* U_i  = (const float*)d_in[12];
    const float* b_i  = (const float*)d_in[13];
    const float* U_ste= (const float*)d_in[14];
    const float* b_ste= (const float*)d_in[15];
    const float* U_fre= (const float*)d_in[16];
    const float* b_fre= (const float*)d_in[17];
    const float* U_c  = (const float*)d_in[18];
    const float* b_c  = (const float*)d_in[19];
    const float* U_o  = (const float*)d_in[20];
    const float* b_o  = (const float*)d_in[21];
    const float* U_a  = (const float*)d_in[22];
    const float* b_a  = (const float*)d_in[23];
    const float* W_p  = (const float*)d_in[24];
    const float* b_p  = (const float*)d_in[25];
    const float* fc_w = (const float*)d_in[26];
    const float* fc_b = (const float*)d_in[27];
    float* out = (float*)d_out;

    static bool attr_set = false;
    if (!attr_set) {
        cudaFuncSetAttribute(step_kernel, cudaFuncAttributeMaxDynamicSharedMemorySize,
                             STEP_SMEM_FLOATS * 4);
        attr_set = true;
    }

    init_kernel<<<148, 256>>>();
    proj_kernel<<<dim3(17, 4, 128), 128>>>(sig, met, Wis, Wss, Wfs, Wcs, Wos,
                                           Wim, Wsm, Wfm, Wcm, Wom,
                                           b_i, b_ste, b_fre, b_c, b_o);
    for (int t = 0; t < TT; t++) {
        step_kernel<<<dim3(8, 16), 128, STEP_SMEM_FLOATS * 4>>>(
            t, U_i, U_ste, U_c, U_o, U_fre, U_a, b_a);
    }
    final_kernel<<<1, 256>>>(W_p, b_p, fc_w, fc_b, out);
}

// round 3
// speedup vs baseline: 2.5274x; 2.5274x over previous
#include <cuda_runtime.h>
#include <math.h>

#define BB 256
#define TT 128
#define HH 256
#define FF 16
#define GG 1040   // 4*H + F

// ---- static device scratch ----
__device__ float g_xproj[TT * GG * BB];   // [t][g][b]
__device__ float g_h[2][HH * BB];         // [j][b], double buffered
__device__ unsigned g_bar;                // grid barrier counter

__device__ __forceinline__ float hsig(float x) {
    return __saturatef(x * 0.16666667f + 0.5f);
}

// ---------------- init ----------------
__global__ void init_kernel() {
    int i = blockIdx.x * blockDim.x + threadIdx.x;
    int n = blockDim.x * gridDim.x;
    for (int k = i; k < 2 * HH * BB; k += n) (&g_h[0][0])[k] = 0.f;
    if (i == 0) g_bar = 0u;
}

// ---------------- phase 0: input projection ----------------
// xproj[t][g][b] = sum_k X[b,t,k] * W[k,g] + bias[g]
__global__ void proj_kernel(
    const float* __restrict__ sig, const float* __restrict__ met,
    const float* __restrict__ Wis, const float* __restrict__ Wss, const float* __restrict__ Wfs,
    const float* __restrict__ Wcs, const float* __restrict__ Wos,
    const float* __restrict__ Wim, const float* __restrict__ Wsm, const float* __restrict__ Wfm,
    const float* __restrict__ Wcm, const float* __restrict__ Wom,
    const float* __restrict__ b_i, const float* __restrict__ b_ste, const float* __restrict__ b_fre,
    const float* __restrict__ b_c, const float* __restrict__ b_o)
{
    __shared__ float A_s[96 * 64];   // [k][b]
    __shared__ float B_s[96 * 64];   // [k][n]
    const int n0 = blockIdx.x * 64;
    const int b0 = blockIdx.y * 64;
    const int t  = blockIdx.z;
    const int tid = threadIdx.x;

    for (int idx = tid; idx < 64 * 96; idx += 128) {
        int b = idx / 96, k = idx - b * 96;
        float v = (k < 64) ? sig[((b0 + b) * TT + t) * 64 + k]
                           : met[((b0 + b) * TT + t) * 32 + (k - 64)];
        A_s[k * 64 + b] = v;
    }
    for (int idx = tid; idx < 96 * 64; idx += 128) {
        int k = idx >> 6, n = idx & 63;
        int g = n0 + n;
        float v = 0.f;
        if (g < 1024) {
            int gate = g >> 8, j = g & 255;
            const float* Ws = (gate == 0) ? Wis : (gate == 1) ? Wss : (gate == 2) ? Wcs : Wos;
            const float* Wm = (gate == 0) ? Wim : (gate == 1) ? Wsm : (gate == 2) ? Wcm : Wom;
            v = (k < 64) ? Ws[k * 256 + j] : Wm[(k - 64) * 256 + j];
        } else if (g < 1040) {
            int f = g - 1024;
            v = (k < 64) ? Wfs[k * 16 + f] : Wfm[(k - 64) * 16 + f];
        }
        B_s[k * 64 + n] = v;
    }
    __syncthreads();

    const int tm = tid & 7, tn = tid >> 3;
    const int mb = tm * 8, nb = tn * 4;
    float acc[8][4] = {};
    for (int k = 0; k < 96; k++) {
        float4 a0 = *(const float4*)&A_s[k * 64 + mb];
        float4 a1 = *(const float4*)&A_s[k * 64 + mb + 4];
        float4 bv = *(const float4*)&B_s[k * 64 + nb];
        float am[8] = {a0.x, a0.y, a0.z, a0.w, a1.x, a1.y, a1.z, a1.w};
#pragma unroll
        for (int i = 0; i < 8; i++) {
            acc[i][0] += am[i] * bv.x; acc[i][1] += am[i] * bv.y;
            acc[i][2] += am[i] * bv.z; acc[i][3] += am[i] * bv.w;
        }
    }
#pragma unroll
    for (int q = 0; q < 4; q++) {
        int g = n0 + nb + q;
        if (g >= GG) continue;
        float bias;
        if (g < 1024) {
            int gate = g >> 8, j = g & 255;
            bias = (gate == 0) ? b_i[j] : (gate == 1) ? b_ste[j] : (gate == 2) ? b_c[j] : b_o[j];
        } else {
            bias = b_fre[g - 1024];
        }
        float4 w0, w1;
        w0.x = acc[0][q] + bias; w0.y = acc[1][q] + bias;
        w0.z = acc[2][q] + bias; w0.w = acc[3][q] + bias;
        w1.x = acc[4][q] + bias; w1.y = acc[5][q] + bias;
        w1.z = acc[6][q] + bias; w1.w = acc[7][q] + bias;
        float* dst = &g_xproj[(t * GG + g) * BB + b0 + mb];
        *(float4*)dst = w0;
        *(float4*)(dst + 4) = w1;
    }
}

// ---------------- persistent recurrence kernel ----------------
// 128 CTAs (8 b-tiles x 16 j-tiles), 256 threads, all 128 steps in one launch.
// smem layout (floats):
#define PS_U    0                       // [k=256][80]: cols 0-63 gates (gate*16+jj), 64-79 fre
#define PS_H    (PS_U + 256 * 80)       // [k=256][36]  h for this b-tile
#define PS_GT   (PS_H + 256 * 36)       // [80][33]     GEMM outputs [g][b]
#define PS_X    (PS_GT + 80 * 33)       // [2560]       xproj slice: gates 2048 + fre 512
#define PS_RE   (PS_X + 2560)
#define PS_IM   (PS_RE + 16)
#define PS_UA   (PS_IM + 16)
#define PS_BA   (PS_UA + 16)
#define PS_TOTAL (PS_BA + 16)

__global__ void __launch_bounds__(256, 1) persist_kernel(
    const float* __restrict__ U_i, const float* __restrict__ U_ste,
    const float* __restrict__ U_c, const float* __restrict__ U_o,
    const float* __restrict__ U_fre, const float* __restrict__ U_a,
    const float* __restrict__ b_a)
{
    extern __shared__ float sm[];
    float* U_s  = sm + PS_U;
    float* h_s  = sm + PS_H;
    float* gt_s = sm + PS_GT;
    float* x_s  = sm + PS_X;
    float* re_s = sm + PS_RE;
    float* im_s = sm + PS_IM;
    float* Ua_s = sm + PS_UA;
    float* ba_s = sm + PS_BA;

    const int tid = threadIdx.x;
    const int bt = blockIdx.x & 7, jt = blockIdx.x >> 3;
    const int b0 = bt * 32, j0 = jt * 16;

    // ---- one-time staging of U columns ----
    for (int idx = tid; idx < 256 * 64; idx += 256) {
        int k = idx >> 6, g = idx & 63;
        int gate = g >> 4, jj = g & 15;
        const float* U = (gate == 0) ? U_i : (gate == 1) ? U_ste : (gate == 2) ? U_c : U_o;
        U_s[k * 80 + g] = U[k * 256 + j0 + jj];
    }
    for (int idx = tid; idx < 256 * 16; idx += 256) {
        int k = idx >> 4, f = idx & 15;
        U_s[k * 80 + 64 + f] = U_fre[k * 16 + f];
    }
    if (tid < 16) { Ua_s[tid] = U_a[tid]; ba_s[tid] = b_a[j0 + tid]; }

    // ---- S state in registers: 2 (b,j) pairs x 16 f ----
    float Sre[2][16], Sim[2][16];
#pragma unroll
    for (int p = 0; p < 2; p++)
#pragma unroll
        for (int f = 0; f < 16; f++) { Sre[p][f] = 0.f; Sim[p][f] = 0.f; }

    const int c_jj = tid >> 4;   // consumer j within tile
    const int c_b  = tid & 15;   // consumer base b

    for (int t = 0; t < TT; t++) {
        // ---- stage h (L2-only loads; L1 is stale across steps) ----
        const float* hin = &g_h[t & 1][0];
        for (int idx = tid; idx < 256 * 32; idx += 256) {
            int b = idx & 31, k = idx >> 5;
            h_s[k * 36 + b] = __ldcg(&hin[k * 256 + b0 + b]);
        }
        __syncthreads();

        if (tid < 128) {
            // ---- gates GEMM: 32b x 64g, 4b x 4g per thread ----
            const int bg = tid >> 4, gg = tid & 15;
            const float* hp = h_s + bg * 4;
            const float* up = U_s + gg * 4;
            float acc[4][4] = {};
#pragma unroll 4
            for (int k = 0; k < 256; k++) {
                float4 hv = *(const float4*)(hp + k * 36);
                float4 uv = *(const float4*)(up + k * 80);
                acc[0][0] += hv.x * uv.x; acc[0][1] += hv.x * uv.y; acc[0][2] += hv.x * uv.z; acc[0][3] += hv.x * uv.w;
                acc[1][0] += hv.y * uv.x; acc[1][1] += hv.y * uv.y; acc[1][2] += hv.y * uv.z; acc[1][3] += hv.y * uv.w;
                acc[2][0] += hv.z * uv.x; acc[2][1] += hv.z * uv.y; acc[2][2] += hv.z * uv.z; acc[2][3] += hv.z * uv.w;
                acc[3][0] += hv.w * uv.x; acc[3][1] += hv.w * uv.y; acc[3][2] += hv.w * uv.z; acc[3][3] += hv.w * uv.w;
            }
#pragma unroll
            for (int q = 0; q < 4; q++)
#pragma unroll
                for (int i = 0; i < 4; i++)
                    gt_s[(gg * 4 + q) * 33 + bg * 4 + i] = acc[i][q];
        } else {
            const int s = tid - 128;
            // ---- prefetch this step's xproj slice (DRAM) into smem ----
            const int xt = t * GG * BB;
            for (int idx = s; idx < 2048; idx += 128) {
                int gate = idx >> 9, jj = (idx >> 5) & 15, b = idx & 31;
                x_s[idx] = g_xproj[xt + (gate * 256 + j0 + jj) * BB + b0 + b];
            }
            for (int idx = s; idx < 512; idx += 128) {
                int f = idx >> 5, b = idx & 31;
                x_s[2048 + idx] = g_xproj[xt + (1024 + f) * BB + b0 + b];
            }
            if (s < 16) {
                float ang = 6.2831855f * (float)(t + 1) * ((float)s * 0.0625f);
                float sv, cv;
                sincosf(ang, &sv, &cv);
                re_s[s] = cv; im_s[s] = sv;
            }
            // ---- fre matvec: 32b x 16f, 1b x 4f per thread ----
            const int fb = s >> 2, f0 = (s & 3) * 4;
            const float* up = U_s + 64 + f0;
            float fa0 = 0.f, fa1 = 0.f, fa2 = 0.f, fa3 = 0.f;
#pragma unroll 4
            for (int k = 0; k < 256; k++) {
                float hk = h_s[k * 36 + fb];
                float4 uv = *(const float4*)(up + k * 80);
                fa0 += hk * uv.x; fa1 += hk * uv.y; fa2 += hk * uv.z; fa3 += hk * uv.w;
            }
            gt_s[(64 + f0 + 0) * 33 + fb] = fa0;
            gt_s[(64 + f0 + 1) * 33 + fb] = fa1;
            gt_s[(64 + f0 + 2) * 33 + fb] = fa2;
            gt_s[(64 + f0 + 3) * 33 + fb] = fa3;
        }
        __syncthreads();

        // ---- consumer: S update (registers) + h output ----
        float* hout = &g_h[(t & 1) ^ 1][0];
#pragma unroll
        for (int p = 0; p < 2; p++) {
            const int b = c_b + p * 16;
            float gi  = hsig(gt_s[(     c_jj) * 33 + b] + x_s[(     c_jj) * 32 + b]);
            float ste = hsig(gt_s[(16 + c_jj) * 33 + b] + x_s[(16 + c_jj) * 32 + b]);
            float cg  = gi * tanhf(gt_s[(32 + c_jj) * 33 + b] + x_s[(32 + c_jj) * 32 + b]);
            float o   = hsig(gt_s[(48 + c_jj) * 33 + b] + x_s[(48 + c_jj) * 32 + b]);
            float Aa = 0.f;
#pragma unroll
            for (int f = 0; f < 16; f++) {
                float fre = hsig(gt_s[(64 + f) * 33 + b] + x_s[2048 + f * 32 + b]);
                float fv = ste * fre;
                float nr = fv * Sre[p][f] + cg * re_s[f];
                float ni = fv * Sim[p][f] + cg * im_s[f];
                Sre[p][f] = nr; Sim[p][f] = ni;
                Aa += (nr * nr + ni * ni) * Ua_s[f];
            }
            float a = tanhf(Aa + ba_s[c_jj]);
            __stcg(&hout[(j0 + c_jj) * 256 + b0 + b], o * a);
        }

        // ---- grid barrier ----
        __threadfence();
        __syncthreads();
        if (tid == 0) {
            atomicAdd(&g_bar, 1u);
            const unsigned target = 128u * (unsigned)(t + 1);
            while (atomicAdd(&g_bar, 0u) < target) { }
        }
        __syncthreads();
    }
}

// ---------------- output head ----------------
__global__ void final_kernel(const float* __restrict__ W_p, const float* __restrict__ b_p,
                             const float* __restrict__ fc_w, const float* __restrict__ fc_b,
                             float* __restrict__ out)
{
    int b = threadIdx.x;
    const float* h = &g_h[0][0];   // after 128 steps (t=127 writes buf 0)
    float s = 0.f;
    for (int j = 0; j < 256; j++) s += h[j * 256 + b] * W_p[j];
    float p = s + b_p[0];
    out[b] = p * fc_w[0] + fc_b[0];
}

// ---------------- launch ----------------
extern "C" void kernel_launch(void* const* d_in, const int* in_sizes, int n_in,
                              void* d_out, int out_size)
{
    const float* sig  = (const float*)d_in[0];
    const float* met  = (const float*)d_in[1];
    const float* Wis  = (const float*)d_in[2];
    const float* Wss  = (const float*)d_in[3];
    const float* Wfs  = (const float*)d_in[4];
    const float* Wcs  = (const float*)d_in[5];
    const float* Wos  = (const float*)d_in[6];
    const float* Wim  = (const float*)d_in[7];
    const float* Wsm  = (const float*)d_in[8];
    const float* Wfm  = (const float*)d_in[9];
    const float* Wcm  = (const float*)d_in[10];
    const float* Wom  = (const float*)d_in[11];
    const float* U_i  = (const float*)d_in[12];
    const float* b_i  = (const float*)d_in[13];
    const float* U_ste= (const float*)d_in[14];
    const float* b_ste= (const float*)d_in[15];
    const float* U_fre= (const float*)d_in[16];
    const float* b_fre= (const float*)d_in[17];
    const float* U_c  = (const float*)d_in[18];
    const float* b_c  = (const float*)d_in[19];
    const float* U_o  = (const float*)d_in[20];
    const float* b_o  = (const float*)d_in[21];
    const float* U_a  = (const float*)d_in[22];
    const float* b_a  = (const float*)d_in[23];
    const float* W_p  = (const float*)d_in[24];
    const float* b_p  = (const float*)d_in[25];
    const float* fc_w = (const float*)d_in[26];
    const float* fc_b = (const float*)d_in[27];
    float* out = (float*)d_out;

    cudaFuncSetAttribute(persist_kernel, cudaFuncAttributeMaxDynamicSharedMemorySize,
                         PS_TOTAL * 4);

    init_kernel<<<148, 256>>>();
    proj_kernel<<<dim3(17, 4, 128), 128>>>(sig, met, Wis, Wss, Wfs, Wcs, Wos,
                                           Wim, Wsm, Wfm, Wcm, Wom,
                                           b_i, b_ste, b_fre, b_c, b_o);
    persist_kernel<<<128, 256, PS_TOTAL * 4>>>(U_i, U_ste, U_c, U_o, U_fre, U_a, b_a);
    final_kernel<<<1, 256>>>(W_p, b_p, fc_w, fc_b, out);
}